// round 5
// baseline (speedup 1.0000x reference)
#include <cuda_runtime.h>
#include <math.h>
#include <stdint.h>

#define BB 128
#define SS 512
#define EE 256
#define HH 512
#define G4 2048   // 4*H
#define TT 32

// ---------------- device scratch (static: no allocations allowed) ----------
static __device__ float g_gx[2][SS][BB][G4];   // x @ W_ih^T + biases, per dir   (1 GB)
static __device__ float g_hs[2][SS][BB][HH];   // masked hidden outputs          (256 MB)
static __device__ float g_hbuf[2][2][BB][HH];  // [parity][dir][b][h] double-buffered h
static __device__ float g_c[2][BB][HH];        // cell state
static __device__ float g_em[SS][BB][TT];      // emissions [t][b][tag]
static __device__ float g_nll[BB];

// ---------------- init --------------------------------------------------
__global__ void zero_kernel() {
    int i = blockIdx.x * blockDim.x + threadIdx.x;
    if (i < 2 * BB * HH) {
        (&g_hbuf[0][0][0][0])[i] = 0.f;   // parity-0 buffer (read at t=0)
        (&g_c[0][0][0])[i]       = 0.f;
    }
}

// ---------------- phase 1: gather + input GEMM --------------------------
// C[m][j] = emb[token(m)] . w_ih[j] + b_ih[j] + b_hh[j],  m = t*128 + b
__global__ void phase1_kernel(const int* __restrict__ sents,
                              const int* __restrict__ lens,
                              const float* __restrict__ emb,
                              const float* __restrict__ w_ih_f,
                              const float* __restrict__ w_ih_b,
                              const float* __restrict__ bih_f,
                              const float* __restrict__ bhh_f,
                              const float* __restrict__ bih_b,
                              const float* __restrict__ bhh_b)
{
    __shared__ float A_s[64][68];
    __shared__ float B_s[64][65];
    const int dir = blockIdx.z;
    const int j0  = blockIdx.x * 64;
    const int m0  = blockIdx.y * 64;
    const float* w = dir ? w_ih_b : w_ih_f;
    const int tid = threadIdx.x;
    const int tx4 = (tid & 15) * 4;
    const int ty4 = (tid >> 4) * 4;

    float acc[4][4];
#pragma unroll
    for (int i = 0; i < 4; ++i)
#pragma unroll
        for (int j = 0; j < 4; ++j) acc[i][j] = 0.f;

    for (int kk = 0; kk < EE; kk += 64) {
        // A tile: gathered embedding rows
#pragma unroll
        for (int it = 0; it < 4; ++it) {
            int f   = tid + it * 256;          // 0..1023 float4 slots
            int row = f >> 4;
            int kf  = (f & 15) << 2;
            int m   = m0 + row;
            int t   = m >> 7;
            int b   = m & 127;
            int tok;
            if (dir == 0) tok = sents[b * SS + t];
            else {
                int L  = lens[b];
                int rt = (t < L) ? (L - 1 - t) : t;
                tok = sents[b * SS + rt];
            }
            float4 a4 = *reinterpret_cast<const float4*>(emb + (size_t)tok * EE + kk + kf);
            *reinterpret_cast<float4*>(&A_s[row][kf]) = a4;
        }
        // B tile (transposed to [k][j])
#pragma unroll
        for (int it = 0; it < 4; ++it) {
            int f  = tid + it * 256;
            int jl = f >> 4;
            int kf = (f & 15) << 2;
            float4 w4 = *reinterpret_cast<const float4*>(w + (size_t)(j0 + jl) * EE + kk + kf);
            B_s[kf + 0][jl] = w4.x;
            B_s[kf + 1][jl] = w4.y;
            B_s[kf + 2][jl] = w4.z;
            B_s[kf + 3][jl] = w4.w;
        }
        __syncthreads();
#pragma unroll
        for (int k4 = 0; k4 < 16; ++k4) {
            float a_reg[4][4];
#pragma unroll
            for (int i = 0; i < 4; ++i) {
                float4 v = *reinterpret_cast<const float4*>(&A_s[ty4 + i][k4 << 2]);
                a_reg[i][0] = v.x; a_reg[i][1] = v.y; a_reg[i][2] = v.z; a_reg[i][3] = v.w;
            }
#pragma unroll
            for (int d = 0; d < 4; ++d) {
                int k = (k4 << 2) + d;
                float b_reg[4];
#pragma unroll
                for (int j = 0; j < 4; ++j) b_reg[j] = B_s[k][tx4 + j];
#pragma unroll
                for (int i = 0; i < 4; ++i)
#pragma unroll
                    for (int j = 0; j < 4; ++j) acc[i][j] += a_reg[i][d] * b_reg[j];
            }
        }
        __syncthreads();
    }

    // biases (same 4 columns for all 4 rows)
    float bias[4];
#pragma unroll
    for (int j = 0; j < 4; ++j) {
        int jg  = j0 + tx4 + j;
        bias[j] = dir ? (bih_b[jg] + bhh_b[jg]) : (bih_f[jg] + bhh_f[jg]);
    }
    float* outp = &g_gx[0][0][0][0] + (size_t)dir * SS * BB * G4;
#pragma unroll
    for (int i = 0; i < 4; ++i) {
        int m = m0 + ty4 + i;
        float4 v;
        v.x = acc[i][0] + bias[0];
        v.y = acc[i][1] + bias[1];
        v.z = acc[i][2] + bias[2];
        v.w = acc[i][3] + bias[3];
        *reinterpret_cast<float4*>(outp + (size_t)m * G4 + j0 + tx4) = v;
    }
}

// ---------------- phase 2: one LSTM step (both directions) ---------------
// block tile: 32 batches x 16 h-units x 4 gates. grid (32, 4, 2).
__global__ void step_kernel(int t,
                            const float* __restrict__ w_hh_f,
                            const float* __restrict__ w_hh_b,
                            const int* __restrict__ lens)
{
    __shared__ float h_s[64][33];
    __shared__ float w_s[64][64];
    __shared__ float gbuf[64][33];
    const int dir = blockIdx.z;
    const int h0  = blockIdx.x * 16;
    const int b0  = blockIdx.y * 32;
    const int tid = threadIdx.x;
    const int bl  = tid & 31;
    const int wr  = tid >> 5;
    const int par = t & 1;
    const float* w     = dir ? w_hh_b : w_hh_f;
    const float* hprev = &g_hbuf[par][dir][0][0];

    float acc[8];
    {
        const float* gx = &g_gx[dir][t][b0 + bl][0];
#pragma unroll
        for (int i = 0; i < 8; ++i) {
            int r = wr * 8 + i;               // r = gate*16 + h_local
            acc[i] = gx[(r >> 4) * HH + h0 + (r & 15)];
        }
    }

    for (int kk = 0; kk < HH; kk += 64) {
#pragma unroll
        for (int it = 0; it < 8; ++it) {
            int e   = tid + it * 256;
            int b_l = e >> 6;
            int k   = e & 63;
            h_s[k][b_l] = hprev[(b0 + b_l) * HH + kk + k];
        }
#pragma unroll
        for (int it = 0; it < 4; ++it) {
            int f  = tid + it * 256;
            int r  = f >> 4;
            int kf = (f & 15) << 2;
            int rg = (r >> 4) * HH + h0 + (r & 15);   // global W_hh row
            *reinterpret_cast<float4*>(&w_s[r][kf]) =
                *reinterpret_cast<const float4*>(w + (size_t)rg * HH + kk + kf);
        }
        __syncthreads();
#pragma unroll
        for (int k4 = 0; k4 < 16; ++k4) {
            float a0 = h_s[(k4 << 2) + 0][bl];
            float a1 = h_s[(k4 << 2) + 1][bl];
            float a2 = h_s[(k4 << 2) + 2][bl];
            float a3 = h_s[(k4 << 2) + 3][bl];
#pragma unroll
            for (int i = 0; i < 8; ++i) {
                float4 w4 = *reinterpret_cast<const float4*>(&w_s[wr * 8 + i][k4 << 2]);
                acc[i] += a0 * w4.x + a1 * w4.y + a2 * w4.z + a3 * w4.w;
            }
        }
        __syncthreads();
    }

#pragma unroll
    for (int i = 0; i < 8; ++i) gbuf[wr * 8 + i][bl] = acc[i];
    __syncthreads();

    float* hnext = &g_hbuf[1 - par][dir][0][0];
#pragma unroll
    for (int c2 = 0; c2 < 2; ++c2) {
        int idx = tid + c2 * 256;
        int h_l = idx & 15;
        int bl2 = idx >> 4;
        int b   = b0 + bl2;
        int hh  = h0 + h_l;
        float gi = gbuf[ 0 + h_l][bl2];
        float gf = gbuf[16 + h_l][bl2];
        float gg = gbuf[32 + h_l][bl2];
        float go = gbuf[48 + h_l][bl2];
        float co = g_c[dir][b][hh];
        float iv = 1.f / (1.f + __expf(-gi));
        float fv = 1.f / (1.f + __expf(-gf));
        float gv = tanhf(gg);
        float ov = 1.f / (1.f + __expf(-go));
        float cn = fv * co + iv * gv;
        float hn = ov * tanhf(cn);
        bool  m  = (t < lens[b]);
        if (m) g_c[dir][b][hh] = cn;
        hnext[b * HH + hh]   = m ? hn : hprev[b * HH + hh];
        g_hs[dir][t][b][hh]  = m ? hn : 0.f;
    }
}

// ---------------- phase 3: emissions -------------------------------------
// one block per (t,b): em[t][b][tag] = [hs_f | hs_b(rev)] . lin_w[tag] + lin_b
__global__ void emis_kernel(const int* __restrict__ lens,
                            const float* __restrict__ lin_w,
                            const float* __restrict__ lin_b)
{
    __shared__ float h_s[2 * HH];
    __shared__ float red[8][TT + 1];
    const int p   = blockIdx.x;
    const int t   = p >> 7;
    const int b   = p & 127;
    const int L   = lens[b];
    const int rt  = (t < L) ? (L - 1 - t) : t;
    const int tid = threadIdx.x;
#pragma unroll
    for (int it = 0; it < 4; ++it) {
        int idx = tid + it * 256;
        h_s[idx] = (idx < HH) ? g_hs[0][t][b][idx] : g_hs[1][rt][b][idx - HH];
    }
    __syncthreads();
    const int tag = tid & 31;
    const int seg = tid >> 5;
    const float4* lw = reinterpret_cast<const float4*>(lin_w + (size_t)tag * 1024 + seg * 128);
    const float*  hh = h_s + seg * 128;
    float acc = 0.f;
#pragma unroll
    for (int q = 0; q < 32; ++q) {
        float4 w4 = __ldg(lw + q);
        acc += hh[q * 4 + 0] * w4.x + hh[q * 4 + 1] * w4.y +
               hh[q * 4 + 2] * w4.z + hh[q * 4 + 3] * w4.w;
    }
    red[seg][tag] = acc;
    __syncthreads();
    if (tid < 32) {
        float s = lin_b[tid];
#pragma unroll
        for (int k = 0; k < 8; ++k) s += red[k][tid];
        g_em[t][b][tid] = s;
    }
}

// ---------------- phase 4: CRF (one warp per batch element) --------------
__global__ void crf_kernel(const int* __restrict__ tags,
                           const int* __restrict__ lens,
                           const float* __restrict__ start,
                           const float* __restrict__ endt,
                           const float* __restrict__ trans)
{
    __shared__ float tr[TT][TT + 1];
    __shared__ float al[TT];
    const int b = blockIdx.x;
    const int j = threadIdx.x;     // 0..31 : tag lane
    for (int i = 0; i < TT; ++i) tr[i][j] = trans[i * TT + j];
    const int L = lens[b];
    int   prev  = tags[b * SS];
    float alpha = start[j] + g_em[0][b][j];
    float score = start[prev] + g_em[0][b][prev];
    __syncwarp();

    for (int t = 1; t < SS; ++t) {
        if (t >= L) break;                       // mask is monotone
        float e  = g_em[t][b][j];
        int   tg = tags[b * SS + t];
        float e_tg = __shfl_sync(0xffffffffu, e, tg);
        score += tr[prev][tg] + e_tg;
        prev = tg;
        al[j] = alpha;
        __syncwarp();
        float v[TT];
        float mx = -1e30f;
#pragma unroll
        for (int i = 0; i < TT; ++i) { v[i] = al[i] + tr[i][j]; mx = fmaxf(mx, v[i]); }
        float sum = 0.f;
#pragma unroll
        for (int i = 0; i < TT; ++i) sum += __expf(v[i] - mx);
        alpha = mx + __logf(sum) + e;
        __syncwarp();
    }

    float num = score + endt[prev];
    float x   = alpha + endt[j];
    float mx  = x;
#pragma unroll
    for (int o = 16; o; o >>= 1) mx = fmaxf(mx, __shfl_xor_sync(0xffffffffu, mx, o));
    float s = __expf(x - mx);
#pragma unroll
    for (int o = 16; o; o >>= 1) s += __shfl_xor_sync(0xffffffffu, s, o);
    float den = mx + __logf(s);
    if (j == 0) g_nll[b] = den - num;
}

// ---------------- final deterministic reduction ---------------------------
__global__ void sum_kernel(float* __restrict__ out) {
    __shared__ float s[BB];
    int t = threadIdx.x;
    s[t] = g_nll[t];
    __syncthreads();
#pragma unroll
    for (int o = 64; o; o >>= 1) {
        if (t < o) s[t] += s[t + o];
        __syncthreads();
    }
    if (t == 0) out[0] = s[0];
}

// ---------------- launch ---------------------------------------------------
extern "C" void kernel_launch(void* const* d_in, const int* in_sizes, int n_in,
                              void* d_out, int out_size) {
    const int*   sents  = (const int*)d_in[0];
    const int*   lens   = (const int*)d_in[1];
    const int*   tags   = (const int*)d_in[2];
    // d_in[3] = mask : recomputed from lengths, unused
    const float* emb    = (const float*)d_in[4];
    const float* w_ih_f = (const float*)d_in[5];
    const float* w_hh_f = (const float*)d_in[6];
    const float* b_ih_f = (const float*)d_in[7];
    const float* b_hh_f = (const float*)d_in[8];
    const float* w_ih_b = (const float*)d_in[9];
    const float* w_hh_b = (const float*)d_in[10];
    const float* b_ih_b = (const float*)d_in[11];
    const float* b_hh_b = (const float*)d_in[12];
    const float* lin_w  = (const float*)d_in[13];
    const float* lin_b  = (const float*)d_in[14];
    const float* startt = (const float*)d_in[15];
    const float* endt   = (const float*)d_in[16];
    const float* trans  = (const float*)d_in[17];
    float* out = (float*)d_out;

    zero_kernel<<<512, 256>>>();
    phase1_kernel<<<dim3(32, 1024, 2), 256>>>(sents, lens, emb, w_ih_f, w_ih_b,
                                              b_ih_f, b_hh_f, b_ih_b, b_hh_b);
    for (int t = 0; t < SS; ++t)
        step_kernel<<<dim3(32, 4, 2), 256>>>(t, w_hh_f, w_hh_b, lens);
    emis_kernel<<<SS * BB, 256>>>(lens, lin_w, lin_b);
    crf_kernel<<<BB, 32>>>(tags, lens, startt, endt, trans);
    sum_kernel<<<1, BB>>>(out);
}

// round 7
// speedup vs baseline: 1.8139x; 1.8139x over previous
#include <cuda_runtime.h>
#include <cuda_bf16.h>
#include <math.h>
#include <stdint.h>

#define BB 128
#define SS 512
#define EE 256
#define HH 512
#define G4 2048   // 4*H
#define TT 32

// ---------------- device scratch (static: no allocations allowed) ----------
static __device__ float g_gx[2][SS][BB][G4];    // x@W_ih^T + biases (natural row idx)
static __device__ float g_hs[2][SS][BB][HH];    // masked hidden outputs (fp32, for emis)
static __device__ float g_cb[2][BB][HH];        // cell state [dir][b][h]
static __device__ float g_em[SS][BB][TT];
static __device__ float g_nll[BB];
// W_hh split bf16 hi/lo, rows REORDERED: R = hblk*64 + gate*16 + hhl
static __device__ __align__(128) __nv_bfloat16 g_wbf[2][2][G4][HH];   // [dir][term][R][k]
// h split bf16 hi/lo, double buffered by parity
static __device__ __align__(128) __nv_bfloat16 g_hbf[2][2][2][BB][HH]; // [par][dir][term][b][k]

// ---------------- PTX helpers ---------------------------------------------
__device__ __forceinline__ uint32_t smem_u32(const void* p) {
    uint32_t a;
    asm("{ .reg .u64 t; cvta.to.shared.u64 t, %1; cvt.u32.u64 %0, t; }" : "=r"(a) : "l"(p));
    return a;
}
#define CPA16(d, s) \
    asm volatile("cp.async.cg.shared.global [%0], [%1], 16;" :: "r"(d), "l"(s) : "memory")
#define CP_COMMIT() asm volatile("cp.async.commit_group;" ::: "memory")
#define CP_WAIT1()  asm volatile("cp.async.wait_group 1;" ::: "memory")
#define CP_WAIT0()  asm volatile("cp.async.wait_group 0;" ::: "memory")
#define LDSM4(r, a) \
    asm volatile("ldmatrix.sync.aligned.m8n8.x4.shared.b16 {%0,%1,%2,%3}, [%4];" \
        : "=r"((r)[0]), "=r"((r)[1]), "=r"((r)[2]), "=r"((r)[3]) : "r"(a))
#define MMA16816(d, a, br0, br1) \
    asm volatile("mma.sync.aligned.m16n8k16.row.col.f32.bf16.bf16.f32 " \
        "{%0,%1,%2,%3}, {%4,%5,%6,%7}, {%8,%9}, {%0,%1,%2,%3};" \
        : "+f"((d)[0]), "+f"((d)[1]), "+f"((d)[2]), "+f"((d)[3]) \
        : "r"((a)[0]), "r"((a)[1]), "r"((a)[2]), "r"((a)[3]), "r"(br0), "r"(br1))

// ---------------- init ------------------------------------------------------
__global__ void zero_kernel() {
    int i = blockIdx.x * blockDim.x + threadIdx.x;        // 131072 threads
    (&g_cb[0][0][0])[i] = 0.f;                            // 2*128*512 floats
    reinterpret_cast<uint32_t*>(&g_hbf[0][0][0][0][0])[i] = 0u;  // parity-0 half
}

// ---------------- W_hh -> bf16 hi/lo, reordered rows -------------------------
__global__ void conv_w_kernel(const float* __restrict__ w_hh_f,
                              const float* __restrict__ w_hh_b) {
    const int p    = blockIdx.x;       // 4096 = dir*2048 + R
    const int dir  = p >> 11;
    const int R    = p & 2047;
    const int hblk = R >> 6;
    const int gate = (R >> 4) & 3;
    const int hhl  = R & 15;
    const int n    = gate * HH + hblk * 16 + hhl;          // natural W_hh row
    const float* w = dir ? w_hh_b : w_hh_f;
    __nv_bfloat16* hi = &g_wbf[dir][0][R][0];
    __nv_bfloat16* lo = &g_wbf[dir][1][R][0];
    for (int k = threadIdx.x; k < HH; k += 256) {
        float v = w[(size_t)n * HH + k];
        __nv_bfloat16 h = __float2bfloat16(v);
        hi[k] = h;
        lo[k] = __float2bfloat16(v - __bfloat162float(h));
    }
}

// ---------------- phase 1: gather + input GEMM (fp32 SIMT) -------------------
__global__ void phase1_kernel(const int* __restrict__ sents,
                              const int* __restrict__ lens,
                              const float* __restrict__ emb,
                              const float* __restrict__ w_ih_f,
                              const float* __restrict__ w_ih_b,
                              const float* __restrict__ bih_f,
                              const float* __restrict__ bhh_f,
                              const float* __restrict__ bih_b,
                              const float* __restrict__ bhh_b)
{
    __shared__ float A_s[64][68];
    __shared__ float B_s[64][65];
    const int dir = blockIdx.z;
    const int j0  = blockIdx.x * 64;
    const int m0  = blockIdx.y * 64;
    const float* w = dir ? w_ih_b : w_ih_f;
    const int tid = threadIdx.x;
    const int tx4 = (tid & 15) * 4;
    const int ty4 = (tid >> 4) * 4;

    float acc[4][4];
#pragma unroll
    for (int i = 0; i < 4; ++i)
#pragma unroll
        for (int j = 0; j < 4; ++j) acc[i][j] = 0.f;

    for (int kk = 0; kk < EE; kk += 64) {
#pragma unroll
        for (int it = 0; it < 4; ++it) {
            int f   = tid + it * 256;
            int row = f >> 4;
            int kf  = (f & 15) << 2;
            int m   = m0 + row;
            int t   = m >> 7;
            int b   = m & 127;
            int tok;
            if (dir == 0) tok = sents[b * SS + t];
            else {
                int L  = lens[b];
                int rt = (t < L) ? (L - 1 - t) : t;
                tok = sents[b * SS + rt];
            }
            float4 a4 = *reinterpret_cast<const float4*>(emb + (size_t)tok * EE + kk + kf);
            *reinterpret_cast<float4*>(&A_s[row][kf]) = a4;
        }
#pragma unroll
        for (int it = 0; it < 4; ++it) {
            int f  = tid + it * 256;
            int jl = f >> 4;
            int kf = (f & 15) << 2;
            float4 w4 = *reinterpret_cast<const float4*>(w + (size_t)(j0 + jl) * EE + kk + kf);
            B_s[kf + 0][jl] = w4.x;
            B_s[kf + 1][jl] = w4.y;
            B_s[kf + 2][jl] = w4.z;
            B_s[kf + 3][jl] = w4.w;
        }
        __syncthreads();
#pragma unroll
        for (int k4 = 0; k4 < 16; ++k4) {
            float a_reg[4][4];
#pragma unroll
            for (int i = 0; i < 4; ++i) {
                float4 v = *reinterpret_cast<const float4*>(&A_s[ty4 + i][k4 << 2]);
                a_reg[i][0] = v.x; a_reg[i][1] = v.y; a_reg[i][2] = v.z; a_reg[i][3] = v.w;
            }
#pragma unroll
            for (int d = 0; d < 4; ++d) {
                int k = (k4 << 2) + d;
                float b_reg[4];
#pragma unroll
                for (int j = 0; j < 4; ++j) b_reg[j] = B_s[k][tx4 + j];
#pragma unroll
                for (int i = 0; i < 4; ++i)
#pragma unroll
                    for (int j = 0; j < 4; ++j) acc[i][j] += a_reg[i][d] * b_reg[j];
            }
        }
        __syncthreads();
    }

    float bias[4];
#pragma unroll
    for (int j = 0; j < 4; ++j) {
        int jg  = j0 + tx4 + j;
        bias[j] = dir ? (bih_b[jg] + bhh_b[jg]) : (bih_f[jg] + bhh_f[jg]);
    }
    float* outp = &g_gx[0][0][0][0] + (size_t)dir * SS * BB * G4;
#pragma unroll
    for (int i = 0; i < 4; ++i) {
        int m = m0 + ty4 + i;
        float4 v;
        v.x = acc[i][0] + bias[0];
        v.y = acc[i][1] + bias[1];
        v.z = acc[i][2] + bias[2];
        v.w = acc[i][3] + bias[3];
        *reinterpret_cast<float4*>(outp + (size_t)m * G4 + j0 + tx4) = v;
    }
}

// ---------------- phase 2: LSTM step via mma.sync bf16x3 ---------------------
// grid 128: dir(2) x hblk(32) x btile(2). block 128 thr = 4 warps.
// block tile: 64 gate-rows (reordered) x 64 batch; warp tile 32x32.
// smem: two 32KB stages: A[2][64][64] bf16 (16KB) + B[2][64][64] bf16 (16KB).
__device__ __forceinline__ void step_issue(uint32_t st, int k0, int tid, int R0, int b0,
                                           const __nv_bfloat16* wsrc,
                                           const __nv_bfloat16* hsrc) {
#pragma unroll
    for (int i = 0; i < 16; ++i) {
        int idx = tid + i * 128;                  // 0..2047
        if (idx < 1024) {                         // A: W tiles
            int T = idx >> 9, rem = idx & 511, r = rem >> 3, g = rem & 7;
            const __nv_bfloat16* src = wsrc + ((size_t)T * G4 + R0 + r) * HH + k0 + g * 8;
            uint32_t dst = st + T * 8192 + r * 128 + (((g ^ (r & 7))) << 4);
            CPA16(dst, src);
        } else {                                  // B: h tiles
            int j = idx - 1024;
            int T = j >> 9, rem = j & 511, r = rem >> 3, g = rem & 7;
            const __nv_bfloat16* src = hsrc + ((size_t)T * BB + b0 + r) * HH + k0 + g * 8;
            uint32_t dst = st + 16384 + T * 8192 + r * 128 + (((g ^ (r & 7))) << 4);
            CPA16(dst, src);
        }
    }
    CP_COMMIT();
}

__global__ void __launch_bounds__(128)
step_mma_kernel(int t, const int* __restrict__ lens)
{
    extern __shared__ float smem_f[];
    const uint32_t sb = smem_u32(smem_f);
    const int tid  = threadIdx.x;
    const int lane = tid & 31;
    const int wid  = tid >> 5;
    const int dir   = blockIdx.x >> 6;
    const int hblk  = (blockIdx.x >> 1) & 31;
    const int btile = blockIdx.x & 1;
    const int par = t & 1;
    const int b0  = btile * 64;
    const int R0  = hblk * 64;

    const __nv_bfloat16* wsrc = &g_wbf[dir][0][0][0];
    const __nv_bfloat16* hsrc = &g_hbf[par][dir][0][0][0];

    const int warp_r = wid >> 1;    // 0..1
    const int warp_b = wid & 1;     // 0..1
    const int a_r  = (lane & 7) + ((lane >> 3) & 1) * 8;   // row in 16-tile
    const int a_kh = lane >> 4;                            // k-half
    const int b_n  = ((lane >> 4) << 3) + (lane & 7);      // n in 16-group
    const int b_kh = (lane >> 3) & 1;

    float acc[2][4][4];
#pragma unroll
    for (int mt = 0; mt < 2; ++mt)
#pragma unroll
        for (int j = 0; j < 4; ++j)
#pragma unroll
            for (int q = 0; q < 4; ++q) acc[mt][j][q] = 0.f;

    step_issue(sb, 0, tid, R0, b0, wsrc, hsrc);

    for (int c = 0; c < 8; ++c) {
        if (c < 7) {
            step_issue(sb + ((c + 1) & 1) * 32768, (c + 1) * 64, tid, R0, b0, wsrc, hsrc);
            CP_WAIT1();
        } else {
            CP_WAIT0();
        }
        __syncthreads();
        const uint32_t st = sb + (c & 1) * 32768;
#pragma unroll
        for (int kq = 0; kq < 4; ++kq) {
            uint32_t Af[2][2][4], Bf[2][2][4];
#pragma unroll
            for (int T = 0; T < 2; ++T) {
#pragma unroll
                for (int mt = 0; mt < 2; ++mt) {
                    int row = warp_r * 32 + mt * 16 + a_r;
                    uint32_t ad = st + T * 8192 + row * 128 +
                                  ((((kq << 1) + a_kh) ^ (row & 7)) << 4);
                    LDSM4(Af[T][mt], ad);
                }
#pragma unroll
                for (int bt = 0; bt < 2; ++bt) {
                    int n = warp_b * 32 + bt * 16 + b_n;
                    uint32_t bd = st + 16384 + T * 8192 + n * 128 +
                                  ((((kq << 1) + b_kh) ^ (n & 7)) << 4);
                    LDSM4(Bf[T][bt], bd);
                }
            }
#pragma unroll
            for (int mt = 0; mt < 2; ++mt)
#pragma unroll
                for (int j = 0; j < 4; ++j) {
                    int bt = j >> 1, hs2 = (j & 1) * 2;
                    MMA16816(acc[mt][j], Af[0][mt], Bf[0][bt][hs2], Bf[0][bt][hs2 + 1]);
                    MMA16816(acc[mt][j], Af[1][mt], Bf[0][bt][hs2], Bf[0][bt][hs2 + 1]);
                    MMA16816(acc[mt][j], Af[0][mt], Bf[1][bt][hs2], Bf[1][bt][hs2 + 1]);
                }
        }
        __syncthreads();
    }

    // stage C to smem (overlaps stage0, all compute finished)
    float* gbuf = smem_f;   // [64][68]
    {
        int r_q = lane >> 2, c_q = (lane & 3) * 2;
#pragma unroll
        for (int mt = 0; mt < 2; ++mt)
#pragma unroll
            for (int j = 0; j < 4; ++j) {
                int lr  = warp_r * 32 + mt * 16 + r_q;
                int col = warp_b * 32 + j * 8 + c_q;
                gbuf[lr * 68 + col]           = acc[mt][j][0];
                gbuf[lr * 68 + col + 1]       = acc[mt][j][1];
                gbuf[(lr + 8) * 68 + col]     = acc[mt][j][2];
                gbuf[(lr + 8) * 68 + col + 1] = acc[mt][j][3];
            }
    }
    __syncthreads();

    // epilogue: 128 threads cover 16 h x 64 b, 8 h each
    const int blc  = tid & 63;
    const int hgrp = tid >> 6;
    const int b    = b0 + blc;
    const int L    = lens[b];
    const bool msk = (t < L);
    const int hbase = hblk * 16 + hgrp * 8;
    const float* gx = &g_gx[dir][t][b][0];
    float* cb = &g_cb[dir][b][0];
    float hsv[8], cnv[8];
    uint32_t phi[4], plo[4];
#pragma unroll
    for (int i = 0; i < 8; ++i) {
        int h_l = hgrp * 8 + i;
        int hh  = hblk * 16 + h_l;
        float gi = gbuf[( 0 + h_l) * 68 + blc] + gx[0 * HH + hh];
        float gf = gbuf[(16 + h_l) * 68 + blc] + gx[1 * HH + hh];
        float gg = gbuf[(32 + h_l) * 68 + blc] + gx[2 * HH + hh];
        float go = gbuf[(48 + h_l) * 68 + blc] + gx[3 * HH + hh];
        float co = cb[hbase + i];
        float iv = 1.f / (1.f + __expf(-gi));
        float fv = 1.f / (1.f + __expf(-gf));
        float gv = tanhf(gg);
        float ov = 1.f / (1.f + __expf(-go));
        float cn = fv * co + iv * gv;
        float hn = ov * tanhf(cn);
        cnv[i] = cn;
        hsv[i] = msk ? hn : 0.f;
        __nv_bfloat16 bh   = __float2bfloat16(hn);
        __nv_bfloat16 blo6 = __float2bfloat16(hn - __bfloat162float(bh));
        uint32_t uh = (uint32_t)__bfloat16_as_ushort(bh);
        uint32_t ul = (uint32_t)__bfloat16_as_ushort(blo6);
        if (i & 1) { phi[i >> 1] |= uh << 16; plo[i >> 1] |= ul << 16; }
        else       { phi[i >> 1]  = uh;       plo[i >> 1]  = ul;       }
    }
    if (msk) {
        *reinterpret_cast<float4*>(cb + hbase)     = make_float4(cnv[0], cnv[1], cnv[2], cnv[3]);
        *reinterpret_cast<float4*>(cb + hbase + 4) = make_float4(cnv[4], cnv[5], cnv[6], cnv[7]);
    }
    *reinterpret_cast<float4*>(&g_hs[dir][t][b][hbase])     = make_float4(hsv[0], hsv[1], hsv[2], hsv[3]);
    *reinterpret_cast<float4*>(&g_hs[dir][t][b][hbase + 4]) = make_float4(hsv[4], hsv[5], hsv[6], hsv[7]);
    *reinterpret_cast<uint4*>(&g_hbf[1 - par][dir][0][b][hbase]) = make_uint4(phi[0], phi[1], phi[2], phi[3]);
    *reinterpret_cast<uint4*>(&g_hbf[1 - par][dir][1][b][hbase]) = make_uint4(plo[0], plo[1], plo[2], plo[3]);
}

// ---------------- phase 3: emissions ----------------------------------------
__global__ void emis_kernel(const int* __restrict__ lens,
                            const float* __restrict__ lin_w,
                            const float* __restrict__ lin_b)
{
    __shared__ float h_s[2 * HH];
    __shared__ float red[8][TT + 1];
    const int p   = blockIdx.x;
    const int t   = p >> 7;
    const int b   = p & 127;
    const int L   = lens[b];
    const int rt  = (t < L) ? (L - 1 - t) : t;
    const int tid = threadIdx.x;
#pragma unroll
    for (int it = 0; it < 4; ++it) {
        int idx = tid + it * 256;
        h_s[idx] = (idx < HH) ? g_hs[0][t][b][idx] : g_hs[1][rt][b][idx - HH];
    }
    __syncthreads();
    const int tag = tid & 31;
    const int seg = tid >> 5;
    const float4* lw = reinterpret_cast<const float4*>(lin_w + (size_t)tag * 1024 + seg * 128);
    const float*  hh = h_s + seg * 128;
    float acc = 0.f;
#pragma unroll
    for (int q = 0; q < 32; ++q) {
        float4 w4 = __ldg(lw + q);
        acc += hh[q * 4 + 0] * w4.x + hh[q * 4 + 1] * w4.y +
               hh[q * 4 + 2] * w4.z + hh[q * 4 + 3] * w4.w;
    }
    red[seg][tag] = acc;
    __syncthreads();
    if (tid < 32) {
        float s = lin_b[tid];
#pragma unroll
        for (int k = 0; k < 8; ++k) s += red[k][tid];
        g_em[t][b][tid] = s;
    }
}

// ---------------- phase 4: CRF ----------------------------------------------
__global__ void crf_kernel(const int* __restrict__ tags,
                           const int* __restrict__ lens,
                           const float* __restrict__ start,
                           const float* __restrict__ endt,
                           const float* __restrict__ trans)
{
    __shared__ float tr[TT][TT + 1];
    __shared__ float al[TT];
    const int b = blockIdx.x;
    const int j = threadIdx.x;
    for (int i = 0; i < TT; ++i) tr[i][j] = trans[i * TT + j];
    const int L = lens[b];
    int   prev  = tags[b * SS];
    float alpha = start[j] + g_em[0][b][j];
    float score = start[prev] + g_em[0][b][prev];
    __syncwarp();

    for (int t = 1; t < SS; ++t) {
        if (t >= L) break;
        float e  = g_em[t][b][j];
        int   tg = tags[b * SS + t];
        float e_tg = __shfl_sync(0xffffffffu, e, tg);
        score += tr[prev][tg] + e_tg;
        prev = tg;
        al[j] = alpha;
        __syncwarp();
        float v[TT];
        float mx = -1e30f;
#pragma unroll
        for (int i = 0; i < TT; ++i) { v[i] = al[i] + tr[i][j]; mx = fmaxf(mx, v[i]); }
        float sum = 0.f;
#pragma unroll
        for (int i = 0; i < TT; ++i) sum += __expf(v[i] - mx);
        alpha = mx + __logf(sum) + e;
        __syncwarp();
    }

    float num = score + endt[prev];
    float x   = alpha + endt[j];
    float mx  = x;
#pragma unroll
    for (int o = 16; o; o >>= 1) mx = fmaxf(mx, __shfl_xor_sync(0xffffffffu, mx, o));
    float s = __expf(x - mx);
#pragma unroll
    for (int o = 16; o; o >>= 1) s += __shfl_xor_sync(0xffffffffu, s, o);
    float den = mx + __logf(s);
    if (j == 0) g_nll[b] = den - num;
}

__global__ void sum_kernel(float* __restrict__ out) {
    __shared__ float s[BB];
    int t = threadIdx.x;
    s[t] = g_nll[t];
    __syncthreads();
#pragma unroll
    for (int o = 64; o; o >>= 1) {
        if (t < o) s[t] += s[t + o];
        __syncthreads();
    }
    if (t == 0) out[0] = s[0];
}

// ---------------- launch -----------------------------------------------------
extern "C" void kernel_launch(void* const* d_in, const int* in_sizes, int n_in,
                              void* d_out, int out_size) {
    const int*   sents  = (const int*)d_in[0];
    const int*   lens   = (const int*)d_in[1];
    const int*   tags   = (const int*)d_in[2];
    const float* emb    = (const float*)d_in[4];
    const float* w_ih_f = (const float*)d_in[5];
    const float* w_hh_f = (const float*)d_in[6];
    const float* b_ih_f = (const float*)d_in[7];
    const float* b_hh_f = (const float*)d_in[8];
    const float* w_ih_b = (const float*)d_in[9];
    const float* w_hh_b = (const float*)d_in[10];
    const float* b_ih_b = (const float*)d_in[11];
    const float* b_hh_b = (const float*)d_in[12];
    const float* lin_w  = (const float*)d_in[13];
    const float* lin_b  = (const float*)d_in[14];
    const float* startt = (const float*)d_in[15];
    const float* endt   = (const float*)d_in[16];
    const float* trans  = (const float*)d_in[17];
    float* out = (float*)d_out;

    cudaFuncSetAttribute(step_mma_kernel, cudaFuncAttributeMaxDynamicSharedMemorySize, 65536);

    zero_kernel<<<512, 256>>>();
    conv_w_kernel<<<4096, 256>>>(w_hh_f, w_hh_b);
    phase1_kernel<<<dim3(32, 1024, 2), 256>>>(sents, lens, emb, w_ih_f, w_ih_b,
                                              b_ih_f, b_hh_f, b_ih_b, b_hh_b);
    for (int t = 0; t < SS; ++t)
        step_mma_kernel<<<128, 128, 65536>>>(t, lens);
    emis_kernel<<<SS * BB, 256>>>(lens, lin_w, lin_b);
    crf_kernel<<<BB, 32>>>(tags, lens, startt, endt, trans);
    sum_kernel<<<1, BB>>>(out);
}